// round 8
// baseline (speedup 1.0000x reference)
#include <cuda_runtime.h>
#include <math.h>

#define BATCH 8
#define SEQ   2048
#define DIM   256
#define ROWS  (BATCH*SEQ)          // 16384
#define LOG2E 1.4426950408889634f

// ---------------- scratch (static device globals; no allocation) ----------------
__device__ float g_WT[4*DIM*DIM];   // transposed weights: [d][e] for Wq,Wk,Wv,Wo
__device__ float g_Q[ROWS*DIM];
__device__ float g_K[ROWS*DIM];
__device__ float g_V[ROWS*DIM];
__device__ float g_loc[ROWS*DIM];

__device__ __forceinline__ float fexp2(float x) {
    float y; asm("ex2.approx.ftz.f32 %0, %1;" : "=f"(y) : "f"(x)); return y;
}

#define FMA4(o,a,b) do{ (o).x = fmaf((a),(b).x,(o).x); (o).y = fmaf((a),(b).y,(o).y); \
                        (o).z = fmaf((a),(b).z,(o).z); (o).w = fmaf((a),(b).w,(o).w);}while(0)

// ---------------- weight transpose (tiny; runs once per launch) ----------------
__global__ void transpose_w_kernel(const float* __restrict__ Wq, const float* __restrict__ Wk,
                                   const float* __restrict__ Wv, const float* __restrict__ Wo) {
    const float* W = (blockIdx.x==0)?Wq:((blockIdx.x==1)?Wk:((blockIdx.x==2)?Wv:Wo));
    float* WT = g_WT + (size_t)blockIdx.x*DIM*DIM;
    for (int idx = threadIdx.x; idx < DIM*DIM; idx += blockDim.x) {
        int d = idx >> 8, e = idx & 255;
        WT[idx] = W[e*DIM + d];          // WT[d][e] = W[e][d]
    }
}

// ---------------- shared 64x256 GEMM mainloop:  acc += A[r0:r0+64, :] * WT ----------------
// thread map: tx = tid&15, ty = tid>>4 ; rows 4*ty+i ; cols 4*tx + 64*j + comp
__device__ __forceinline__ void gemm64x256(const float* __restrict__ A, int r0,
                                           const float* __restrict__ WT,
                                           float* Xs /*64x33*/, float* WsT /*32x256*/,
                                           int tx, int ty, int tid, float4 acc[4][4]) {
    for (int dc = 0; dc < 8; ++dc) {
        // stage A tile [64 x 32] (padded rows of 33 to kill bank conflicts on a-loads)
        #pragma unroll
        for (int it = 0; it < 2; ++it) {
            int idx = tid + it*256;          // 0..511
            int r = idx >> 3, d4 = idx & 7;
            float4 v = *(const float4*)(A + (size_t)(r0+r)*DIM + dc*32 + d4*4);
            float* p = &Xs[r*33 + d4*4];
            p[0]=v.x; p[1]=v.y; p[2]=v.z; p[3]=v.w;
        }
        // stage WT chunk [32 x 256] (direct coalesced float4 copy)
        #pragma unroll
        for (int it = 0; it < 8; ++it) {
            int idx = tid + it*256;          // 0..2047
            int dd = idx >> 6, c4 = idx & 63;
            *(float4*)&WsT[dd*256 + c4*4] =
                *(const float4*)(WT + (size_t)(dc*32+dd)*DIM + c4*4);
        }
        __syncthreads();
        #pragma unroll 8
        for (int dd = 0; dd < 32; ++dd) {
            float a[4];
            #pragma unroll
            for (int i = 0; i < 4; ++i) a[i] = Xs[(4*ty+i)*33 + dd];
            #pragma unroll
            for (int j = 0; j < 4; ++j) {
                float4 b = *(float4*)&WsT[dd*256 + 4*tx + 64*j];
                #pragma unroll
                for (int i = 0; i < 4; ++i) FMA4(acc[i][j], a[i], b);
            }
        }
        __syncthreads();
    }
}

// ---------------- QKV projections ----------------
__global__ __launch_bounds__(256) void qkv_kernel(const float* __restrict__ x,
        const float* __restrict__ bq, const float* __restrict__ bk, const float* __restrict__ bv) {
    __shared__ float Xs[64*33];
    __shared__ float WsT[32*256];
    int m = blockIdx.y;
    const float* WT   = g_WT + (size_t)m*DIM*DIM;
    const float* bias = (m==0)?bq:((m==1)?bk:bv);
    float*       outp = (m==0)?g_Q:((m==1)?g_K:g_V);
    int r0 = blockIdx.x*64;
    int tid = threadIdx.x, tx = tid&15, ty = tid>>4;

    float4 acc[4][4];
    #pragma unroll
    for (int i=0;i<4;i++)
        #pragma unroll
        for (int j=0;j<4;j++) acc[i][j] = make_float4(0.f,0.f,0.f,0.f);

    gemm64x256(x, r0, WT, Xs, WsT, tx, ty, tid, acc);

    #pragma unroll
    for (int j=0;j<4;j++){
        float4 bb = *(const float4*)(bias + 4*tx + 64*j);
        #pragma unroll
        for (int i=0;i<4;i++){
            float4 v = acc[i][j];
            v.x+=bb.x; v.y+=bb.y; v.z+=bb.z; v.w+=bb.w;
            *(float4*)(outp + (size_t)(r0+4*ty+i)*DIM + 4*tx + 64*j) = v;
        }
    }
}

// ---------------- fp32 flash attention: 64 queries x 128-key tiles ----------------
// smem: Qs[64][257] | KsT[32][132] | Vs[32][256] | Ps[64][132]   = 149248 B
#define SMEM_ATTN ((64*257 + 32*132 + 32*256 + 64*132) * (int)sizeof(float))

__global__ __launch_bounds__(256) void attn_kernel() {
    extern __shared__ float sm[];
    float* Qs  = sm;                 // 64*257
    float* KsT = Qs  + 64*257;       // 32*132
    float* Vs  = KsT + 32*132;       // 32*256
    float* Ps  = Vs  + 32*256;       // 64*132
    int b  = blockIdx.y;
    int q0 = blockIdx.x*64;
    int tid = threadIdx.x, tx = tid&15, ty = tid>>4;
    const float* Qg = g_Q + (size_t)b*SEQ*DIM;
    const float* Kg = g_K + (size_t)b*SEQ*DIM;
    const float* Vg = g_V + (size_t)b*SEQ*DIM;

    // stage full Q tile [64 x 256] once (row pad 257 -> conflict-free broadcast a-loads)
    #pragma unroll
    for (int it=0; it<16; ++it) {
        int idx = tid + it*256;
        int r = idx >> 6, d4 = idx & 63;
        float4 v = *(const float4*)(Qg + (size_t)(q0+r)*DIM + d4*4);
        float* p = &Qs[r*257 + d4*4];
        p[0]=v.x; p[1]=v.y; p[2]=v.z; p[3]=v.w;
    }
    // (first __syncthreads inside the kt loop orders this before any Qs read)

    float4 o[4][4];
    #pragma unroll
    for (int i=0;i<4;i++)
        #pragma unroll
        for (int j=0;j<4;j++) o[i][j] = make_float4(0.f,0.f,0.f,0.f);
    float mrow[4] = {-INFINITY,-INFINITY,-INFINITY,-INFINITY};
    float lrow[4] = {0.f,0.f,0.f,0.f};

    for (int kt = 0; kt < SEQ/128; ++kt) {
        int k0 = kt*128;
        // ---- S = Q * K^T  (64 x 128), per-thread s[row i][col 4*tx+64*jj+ii] ----
        float s[4][8];
        #pragma unroll
        for (int i=0;i<4;i++)
            #pragma unroll
            for (int c=0;c<8;c++) s[i][c] = 0.f;

        for (int dc = 0; dc < 8; ++dc) {
            // stage transposed K chunk [32 d][128 c] (pad 132)
            #pragma unroll
            for (int it=0; it<4; ++it) {
                int idx = tid + it*256;        // 0..1023
                int c = idx >> 3, d4 = idx & 7;
                float4 v = *(const float4*)(Kg + (size_t)(k0+c)*DIM + dc*32 + d4*4);
                KsT[(d4*4+0)*132 + c] = v.x;
                KsT[(d4*4+1)*132 + c] = v.y;
                KsT[(d4*4+2)*132 + c] = v.z;
                KsT[(d4*4+3)*132 + c] = v.w;
            }
            __syncthreads();
            #pragma unroll 8
            for (int dd = 0; dd < 32; ++dd) {
                float a[4];
                #pragma unroll
                for (int i=0;i<4;i++) a[i] = Qs[(4*ty+i)*257 + dc*32 + dd];
                float4 b0 = *(float4*)&KsT[dd*132 + 4*tx];
                float4 b1 = *(float4*)&KsT[dd*132 + 4*tx + 64];
                #pragma unroll
                for (int i=0;i<4;i++){
                    s[i][0] = fmaf(a[i], b0.x, s[i][0]);
                    s[i][1] = fmaf(a[i], b0.y, s[i][1]);
                    s[i][2] = fmaf(a[i], b0.z, s[i][2]);
                    s[i][3] = fmaf(a[i], b0.w, s[i][3]);
                    s[i][4] = fmaf(a[i], b1.x, s[i][4]);
                    s[i][5] = fmaf(a[i], b1.y, s[i][5]);
                    s[i][6] = fmaf(a[i], b1.z, s[i][6]);
                    s[i][7] = fmaf(a[i], b1.w, s[i][7]);
                }
            }
            __syncthreads();
        }

        // ---- online softmax (row spread across the 16 tx lanes of each half-warp) ----
        #pragma unroll
        for (int i=0;i<4;i++){
            float mx = s[i][0];
            #pragma unroll
            for (int c=1;c<8;c++) mx = fmaxf(mx, s[i][c]);
            #pragma unroll
            for (int off=8; off>=1; off>>=1)
                mx = fmaxf(mx, __shfl_xor_sync(0xffffffffu, mx, off));
            float mnew = fmaxf(mrow[i], mx);
            float corr = fexp2((mrow[i]-mnew)*LOG2E);   // 0 on first tile (m=-inf)
            mrow[i] = mnew;
            float ps = 0.f;
            #pragma unroll
            for (int c=0;c<8;c++){
                float p = fexp2((s[i][c]-mnew)*LOG2E);
                s[i][c] = p; ps += p;
            }
            #pragma unroll
            for (int off=8; off>=1; off>>=1)
                ps += __shfl_xor_sync(0xffffffffu, ps, off);
            lrow[i] = lrow[i]*corr + ps;
            #pragma unroll
            for (int j=0;j<4;j++){
                o[i][j].x*=corr; o[i][j].y*=corr; o[i][j].z*=corr; o[i][j].w*=corr;
            }
            #pragma unroll
            for (int jj=0; jj<2; ++jj)
                #pragma unroll
                for (int ii=0; ii<4; ++ii)
                    Ps[(4*ty+i)*132 + 4*tx + 64*jj + ii] = s[i][jj*4+ii];
        }
        __syncthreads();

        // ---- O += P * V  (accumulate over 128 keys, V staged in 32-key chunks) ----
        for (int vc = 0; vc < 4; ++vc) {
            #pragma unroll
            for (int it=0; it<8; ++it) {
                int idx = tid + it*256;        // 0..2047
                int k = idx >> 6, c4 = idx & 63;
                *(float4*)&Vs[k*256 + c4*4] =
                    *(const float4*)(Vg + (size_t)(k0+vc*32+k)*DIM + c4*4);
            }
            __syncthreads();
            #pragma unroll 8
            for (int kk=0; kk<32; ++kk){
                float a[4];
                #pragma unroll
                for (int i=0;i<4;i++) a[i] = Ps[(4*ty+i)*132 + vc*32 + kk];
                #pragma unroll
                for (int j=0;j<4;j++){
                    float4 bv4 = *(float4*)&Vs[kk*256 + 4*tx + 64*j];
                    #pragma unroll
                    for (int i=0;i<4;i++) FMA4(o[i][j], a[i], bv4);
                }
            }
            __syncthreads();
        }
    }

    // finalize: divide by row sums, write loc
    float* locp = g_loc + (size_t)b*SEQ*DIM;
    #pragma unroll
    for (int i=0;i<4;i++){
        float inv = 1.0f / lrow[i];
        #pragma unroll
        for (int j=0;j<4;j++){
            float4 v = o[i][j];
            v.x*=inv; v.y*=inv; v.z*=inv; v.w*=inv;
            *(float4*)(locp + (size_t)(q0+4*ty+i)*DIM + 4*tx + 64*j) = v;
        }
    }
}

// ---------------- output projection + LayerNorm + LeakyReLU ----------------
__global__ __launch_bounds__(256) void proj_ln_kernel(const float* __restrict__ bo,
        const float* __restrict__ gamma, const float* __restrict__ beta,
        float* __restrict__ out) {
    __shared__ float Xs[64*33];
    __shared__ float WsT[32*256];
    const float* WT = g_WT + (size_t)3*DIM*DIM;
    int r0 = blockIdx.x*64;
    int tid = threadIdx.x, tx = tid&15, ty = tid>>4;

    float4 acc[4][4];
    #pragma unroll
    for (int i=0;i<4;i++)
        #pragma unroll
        for (int j=0;j<4;j++) acc[i][j] = make_float4(0.f,0.f,0.f,0.f);

    gemm64x256(g_loc, r0, WT, Xs, WsT, tx, ty, tid, acc);

    // + bias
    #pragma unroll
    for (int j=0;j<4;j++){
        float4 bb = *(const float4*)(bo + 4*tx + 64*j);
        #pragma unroll
        for (int i=0;i<4;i++){
            acc[i][j].x+=bb.x; acc[i][j].y+=bb.y; acc[i][j].z+=bb.z; acc[i][j].w+=bb.w;
        }
    }

    // LayerNorm per row (row = 4*ty+i, 16 cols per lane, reduce over 16 tx lanes)
    #pragma unroll
    for (int i=0;i<4;i++){
        float ssum = 0.f;
        #pragma unroll
        for (int j=0;j<4;j++) ssum += acc[i][j].x + acc[i][j].y + acc[i][j].z + acc[i][j].w;
        #pragma unroll
        for (int off=8; off>=1; off>>=1) ssum += __shfl_xor_sync(0xffffffffu, ssum, off);
        float mu = ssum * (1.0f/DIM);

        float vsum = 0.f;
        #pragma unroll
        for (int j=0;j<4;j++){
            float dx = acc[i][j].x-mu, dy = acc[i][j].y-mu, dz = acc[i][j].z-mu, dw = acc[i][j].w-mu;
            vsum += dx*dx + dy*dy + dz*dz + dw*dw;
        }
        #pragma unroll
        for (int off=8; off>=1; off>>=1) vsum += __shfl_xor_sync(0xffffffffu, vsum, off);
        float rstd = rsqrtf(vsum*(1.0f/DIM) + 1e-5f);

        #pragma unroll
        for (int j=0;j<4;j++){
            float4 g  = *(const float4*)(gamma + 4*tx + 64*j);
            float4 bt = *(const float4*)(beta  + 4*tx + 64*j);
            float4 h  = acc[i][j];
            float4 y;
            y.x = (h.x-mu)*rstd*g.x + bt.x;  y.x = (y.x>=0.f) ? y.x : 0.01f*y.x;
            y.y = (h.y-mu)*rstd*g.y + bt.y;  y.y = (y.y>=0.f) ? y.y : 0.01f*y.y;
            y.z = (h.z-mu)*rstd*g.z + bt.z;  y.z = (y.z>=0.f) ? y.z : 0.01f*y.z;
            y.w = (h.w-mu)*rstd*g.w + bt.w;  y.w = (y.w>=0.f) ? y.w : 0.01f*y.w;
            *(float4*)(out + (size_t)(r0+4*ty+i)*DIM + 4*tx + 64*j) = y;
        }
    }
}

// ---------------- entry point ----------------
extern "C" void kernel_launch(void* const* d_in, const int* in_sizes, int n_in,
                              void* d_out, int out_size) {
    const float* x     = (const float*)d_in[0];
    const float* Wq    = (const float*)d_in[1];
    const float* bq    = (const float*)d_in[2];
    const float* Wk    = (const float*)d_in[3];
    const float* bk    = (const float*)d_in[4];
    const float* Wv    = (const float*)d_in[5];
    const float* bv    = (const float*)d_in[6];
    const float* Wo    = (const float*)d_in[7];
    const float* bo    = (const float*)d_in[8];
    const float* gamma = (const float*)d_in[9];
    const float* beta  = (const float*)d_in[10];
    float* out = (float*)d_out;

    cudaFuncSetAttribute(attn_kernel, cudaFuncAttributeMaxDynamicSharedMemorySize, SMEM_ATTN);

    transpose_w_kernel<<<4, 256>>>(Wq, Wk, Wv, Wo);
    qkv_kernel<<<dim3(ROWS/64, 3), 256>>>(x, bq, bk, bv);
    attn_kernel<<<dim3(SEQ/64, BATCH), 256, SMEM_ATTN>>>();
    proj_ln_kernel<<<ROWS/64, 256>>>(bo, gamma, beta, out);
}

// round 10
// speedup vs baseline: 1.7048x; 1.7048x over previous
#include <cuda_runtime.h>
#include <cuda_bf16.h>
#include <mma.h>
#include <math.h>
#include <stdint.h>
using namespace nvcuda;

#define BATCH 8
#define SEQ   2048
#define DIM   256
#define ROWS  (BATCH*SEQ)
#define LOG2E 1.4426950408889634f

__device__ __align__(16) float g_WT[4*DIM*DIM];
__device__ __align__(16) float g_loc[ROWS*DIM];
__device__ __align__(16) __nv_bfloat16 g_Qh[ROWS*DIM], g_Ql[ROWS*DIM];
__device__ __align__(16) __nv_bfloat16 g_Kh[ROWS*DIM], g_Kl[ROWS*DIM];
__device__ __align__(16) __nv_bfloat16 g_Vh[ROWS*DIM], g_Vl[ROWS*DIM];

__device__ __forceinline__ float fexp2(float x){ float y; asm("ex2.approx.ftz.f32 %0, %1;" : "=f"(y) : "f"(x)); return y; }
#define FMA4(o,a,b) do{ (o).x=fmaf((a),(b).x,(o).x); (o).y=fmaf((a),(b).y,(o).y); \
                        (o).z=fmaf((a),(b).z,(o).z); (o).w=fmaf((a),(b).w,(o).w);}while(0)

__device__ __forceinline__ uint32_t packbf(__nv_bfloat16 a, __nv_bfloat16 b){
    return (uint32_t)__bfloat16_as_ushort(a) | ((uint32_t)__bfloat16_as_ushort(b)<<16);
}
__device__ __forceinline__ void split4(float4 v, uint2& h, uint2& l){
    __nv_bfloat16 hx=__float2bfloat16(v.x), hy=__float2bfloat16(v.y), hz=__float2bfloat16(v.z), hw=__float2bfloat16(v.w);
    h.x = packbf(hx,hy); h.y = packbf(hz,hw);
    l.x = packbf(__float2bfloat16(v.x-__bfloat162float(hx)), __float2bfloat16(v.y-__bfloat162float(hy)));
    l.y = packbf(__float2bfloat16(v.z-__bfloat162float(hz)), __float2bfloat16(v.w-__bfloat162float(hw)));
}

// ---------------- weight transpose ----------------
__global__ void transpose_w_kernel(const float* __restrict__ Wq, const float* __restrict__ Wk,
                                   const float* __restrict__ Wv, const float* __restrict__ Wo){
    const float* W = (blockIdx.x==0)?Wq:((blockIdx.x==1)?Wk:((blockIdx.x==2)?Wv:Wo));
    float* WT = g_WT + (size_t)blockIdx.x*DIM*DIM;
    for (int idx = threadIdx.x; idx < DIM*DIM; idx += blockDim.x)
        WT[idx] = W[(idx&255)*DIM + (idx>>8)];
}

// ---------------- fp32 64x256 GEMM mainloop ----------------
__device__ __forceinline__ void gemm64x256(const float* __restrict__ A, int r0, const float* __restrict__ WT,
                                           float* Xs, float* WsT, int tx, int ty, int tid, float4 acc[4][4]){
    for (int dc = 0; dc < 8; ++dc){
        #pragma unroll
        for (int it = 0; it < 2; ++it){
            int idx = tid + it*256; int r = idx>>3, d4 = idx&7;
            float4 v = *(const float4*)(A + (size_t)(r0+r)*DIM + dc*32 + d4*4);
            float* p = &Xs[r*33 + d4*4]; p[0]=v.x; p[1]=v.y; p[2]=v.z; p[3]=v.w;
        }
        #pragma unroll
        for (int it = 0; it < 8; ++it){
            int idx = tid + it*256; int dd = idx>>6, c4 = idx&63;
            *(float4*)&WsT[dd*256 + c4*4] = *(const float4*)(WT + (size_t)(dc*32+dd)*DIM + c4*4);
        }
        __syncthreads();
        #pragma unroll 8
        for (int dd = 0; dd < 32; ++dd){
            float a[4];
            #pragma unroll
            for (int i = 0; i < 4; ++i) a[i] = Xs[(4*ty+i)*33 + dd];
            #pragma unroll
            for (int j = 0; j < 4; ++j){
                float4 b = *(float4*)&WsT[dd*256 + 4*tx + 64*j];
                #pragma unroll
                for (int i = 0; i < 4; ++i) FMA4(acc[i][j], a[i], b);
            }
        }
        __syncthreads();
    }
}

// ---------------- QKV projections -> bf16 hi/lo ----------------
__global__ __launch_bounds__(256) void qkv_kernel(const float* __restrict__ x,
        const float* __restrict__ bq, const float* __restrict__ bk, const float* __restrict__ bv){
    __shared__ float Xs[64*33];
    __shared__ float WsT[32*256];
    int m = blockIdx.y;
    const float* WT   = g_WT + (size_t)m*DIM*DIM;
    const float* bias = (m==0)?bq:((m==1)?bk:bv);
    __nv_bfloat16* oh = (m==0)?g_Qh:((m==1)?g_Kh:g_Vh);
    __nv_bfloat16* ol = (m==0)?g_Ql:((m==1)?g_Kl:g_Vl);
    int r0 = blockIdx.x*64;
    int tid = threadIdx.x, tx = tid&15, ty = tid>>4;
    float4 acc[4][4];
    #pragma unroll
    for (int i=0;i<4;i++){ acc[i][0]=acc[i][1]=acc[i][2]=acc[i][3]=make_float4(0.f,0.f,0.f,0.f); }
    gemm64x256(x, r0, WT, Xs, WsT, tx, ty, tid, acc);
    #pragma unroll
    for (int j=0;j<4;j++){
        float4 bb = *(const float4*)(bias + 4*tx + 64*j);
        #pragma unroll
        for (int i=0;i<4;i++){
            float4 v = acc[i][j];
            v.x+=bb.x; v.y+=bb.y; v.z+=bb.z; v.w+=bb.w;
            size_t off = (size_t)(r0+4*ty+i)*DIM + 4*tx + 64*j;
            uint2 h,l; split4(v,h,l);
            *(uint2*)(oh+off) = h; *(uint2*)(ol+off) = l;
        }
    }
}

// ---------------- WMMA bf16-split flash attention ----------------
// q-tile 64, k-tile 64, 8 warps, no max-subtraction softmax (unnormalized exp),
// O fragments persist in registers across all key tiles.
#define QS 264               // bf16/f32 stride for 256-col tiles (ldmatrix conflict-free)
#define PS 72                // stride for 64-col S/P tiles
#define O_QH 0
#define O_QL 33792
#define O_KV 67584           // Kh|Kl, then Vh|Vl, then O (float) reuse
#define O_SS 135168
#define O_PH 153600
#define O_PL 162816
#define O_LS 172032
#define SMEM_ATTN 172416

__device__ __forceinline__ void stage64(__nv_bfloat16* s, const __nv_bfloat16* g, int tid){
    #pragma unroll
    for (int it=0; it<8; ++it){
        int idx = tid + it*256;          // 0..2047 : 64 rows x 32 groups of 8 bf16
        int r = idx>>5, c8 = idx&31;
        *(uint4*)(s + r*QS + c8*8) = *(const uint4*)(g + r*DIM + c8*8);
    }
}

__global__ void __launch_bounds__(256,1) attn_wmma_kernel(){
    extern __shared__ char smch[];
    __nv_bfloat16* Qh = (__nv_bfloat16*)(smch+O_QH);
    __nv_bfloat16* Ql = (__nv_bfloat16*)(smch+O_QL);
    __nv_bfloat16* KVh = (__nv_bfloat16*)(smch+O_KV);
    __nv_bfloat16* KVl = KVh + 64*QS;
    float* Of = (float*)(smch+O_KV);
    float* Ss = (float*)(smch+O_SS);
    __nv_bfloat16* Ph = (__nv_bfloat16*)(smch+O_PH);
    __nv_bfloat16* Pl = (__nv_bfloat16*)(smch+O_PL);
    float* lsum = (float*)(smch+O_LS);

    int tid = threadIdx.x, wid = tid>>5;
    int b = blockIdx.y, q0 = blockIdx.x*64;
    int mw = wid&3, np = wid>>2;

    stage64(Qh, g_Qh + (size_t)(b*SEQ+q0)*DIM, tid);
    stage64(Ql, g_Ql + (size_t)(b*SEQ+q0)*DIM, tid);
    if (tid < 64) lsum[tid] = 0.f;

    wmma::fragment<wmma::accumulator,16,16,16,float> o[8];
    #pragma unroll
    for (int j=0;j<8;j++) wmma::fill_fragment(o[j], 0.f);

    for (int kt = 0; kt < SEQ/64; ++kt){
        size_t kb = (size_t)(b*SEQ + kt*64)*DIM;
        __syncthreads();                       // prev PV reads (and first-iter Q stage) done
        stage64(KVh, g_Kh + kb, tid);
        stage64(KVl, g_Kl + kb, tid);
        __syncthreads();

        // ---- S = (Qh+Ql)*(Kh+Kl)^T : 3 terms ----
        wmma::fragment<wmma::accumulator,16,16,16,float> c[2];
        wmma::fill_fragment(c[0], 0.f);
        wmma::fill_fragment(c[1], 0.f);
        #pragma unroll
        for (int k=0;k<16;++k){
            wmma::fragment<wmma::matrix_a,16,16,16,__nv_bfloat16,wmma::row_major> ah, al;
            wmma::load_matrix_sync(ah, Qh + mw*16*QS + k*16, QS);
            wmma::load_matrix_sync(al, Ql + mw*16*QS + k*16, QS);
            #pragma unroll
            for (int j=0;j<2;++j){
                int n0 = (np*2+j)*16;
                wmma::fragment<wmma::matrix_b,16,16,16,__nv_bfloat16,wmma::col_major> bh, bl;
                wmma::load_matrix_sync(bh, KVh + n0*QS + k*16, QS);
                wmma::load_matrix_sync(bl, KVl + n0*QS + k*16, QS);
                wmma::mma_sync(c[j], ah, bh, c[j]);
                wmma::mma_sync(c[j], al, bh, c[j]);
                wmma::mma_sync(c[j], ah, bl, c[j]);
            }
        }
        #pragma unroll
        for (int j=0;j<2;++j)
            wmma::store_matrix_sync(Ss + mw*16*PS + (np*2+j)*16, c[j], PS, wmma::mem_row_major);
        __syncthreads();

        // ---- softmax: P = exp(S) (unnormalized), split to bf16 hi/lo ----
        {
            int row = tid>>2, part = tid&3;
            const float* sr = Ss + row*PS + part*16;
            __nv_bfloat16* phr = Ph + row*PS + part*16;
            __nv_bfloat16* plr = Pl + row*PS + part*16;
            float psum = 0.f;
            #pragma unroll
            for (int c2=0;c2<16;++c2){
                float p = fexp2(sr[c2]*LOG2E);
                psum += p;
                __nv_bfloat16 h = __float2bfloat16(p);
                phr[c2] = h;
                plr[c2] = __float2bfloat16(p - __bfloat162float(h));
            }
            psum += __shfl_xor_sync(0xffffffffu, psum, 1);
            psum += __shfl_xor_sync(0xffffffffu, psum, 2);
            if (part == 0) lsum[row] += psum;
        }
        __syncthreads();

        // ---- stage V over dead K buffer ----
        stage64(KVh, g_Vh + kb, tid);
        stage64(KVl, g_Vl + kb, tid);
        __syncthreads();

        // ---- O += (Ph+Pl)*(Vh+Vl) : 3 terms, accumulate in registers ----
        #pragma unroll
        for (int k=0;k<4;++k){
            wmma::fragment<wmma::matrix_a,16,16,16,__nv_bfloat16,wmma::row_major> ah, al;
            wmma::load_matrix_sync(ah, Ph + mw*16*PS + k*16, PS);
            wmma::load_matrix_sync(al, Pl + mw*16*PS + k*16, PS);
            #pragma unroll
            for (int j=0;j<8;++j){
                int n0 = (np*8+j)*16;
                wmma::fragment<wmma::matrix_b,16,16,16,__nv_bfloat16,wmma::row_major> bh, bl;
                wmma::load_matrix_sync(bh, KVh + k*16*QS + n0, QS);
                wmma::load_matrix_sync(bl, KVl + k*16*QS + n0, QS);
                wmma::mma_sync(o[j], ah, bh, o[j]);
                wmma::mma_sync(o[j], al, bh, o[j]);
                wmma::mma_sync(o[j], ah, bl, o[j]);
            }
        }
    }

    __syncthreads();                          // all PV reads of KV buffer done
    #pragma unroll
    for (int j=0;j<8;++j)
        wmma::store_matrix_sync(Of + mw*16*QS + (np*8+j)*16, o[j], QS, wmma::mem_row_major);
    __syncthreads();

    {
        int row = tid>>2, part = tid&3;
        float inv = 1.0f / lsum[row];
        const float* orow = Of + row*QS + part*64;
        float* gout = g_loc + (size_t)(b*SEQ+q0+row)*DIM + part*64;
        #pragma unroll
        for (int c4=0;c4<16;++c4){
            float4 v = *(const float4*)(orow + c4*4);
            v.x*=inv; v.y*=inv; v.z*=inv; v.w*=inv;
            *(float4*)(gout + c4*4) = v;
        }
    }
}

// ---------------- output projection + LayerNorm + LeakyReLU ----------------
__global__ __launch_bounds__(256) void proj_ln_kernel(const float* __restrict__ bo,
        const float* __restrict__ gamma, const float* __restrict__ beta, float* __restrict__ out){
    __shared__ float Xs[64*33];
    __shared__ float WsT[32*256];
    const float* WT = g_WT + (size_t)3*DIM*DIM;
    int r0 = blockIdx.x*64;
    int tid = threadIdx.x, tx = tid&15, ty = tid>>4;
    float4 acc[4][4];
    #pragma unroll
    for (int i=0;i<4;i++){ acc[i][0]=acc[i][1]=acc[i][2]=acc[i][3]=make_float4(0.f,0.f,0.f,0.f); }
    gemm64x256(g_loc, r0, WT, Xs, WsT, tx, ty, tid, acc);
    #pragma unroll
    for (int j=0;j<4;j++){
        float4 bb = *(const float4*)(bo + 4*tx + 64*j);
        #pragma unroll
        for (int i=0;i<4;i++){ acc[i][j].x+=bb.x; acc[i][j].y+=bb.y; acc[i][j].z+=bb.z; acc[i][j].w+=bb.w; }
    }
    #pragma unroll
    for (int i=0;i<4;i++){
        float ssum = 0.f;
        #pragma unroll
        for (int j=0;j<4;j++) ssum += acc[i][j].x + acc[i][j].y + acc[i][j].z + acc[i][j].w;
        #pragma unroll
        for (int off=8; off>=1; off>>=1) ssum += __shfl_xor_sync(0xffffffffu, ssum, off);
        float mu = ssum * (1.0f/DIM);
        float vsum = 0.f;
        #pragma unroll
        for (int j=0;j<4;j++){
            float dx=acc[i][j].x-mu, dy=acc[i][j].y-mu, dz=acc[i][j].z-mu, dw=acc[i][j].w-mu;
            vsum += dx*dx + dy*dy + dz*dz + dw*dw;
        }
        #pragma unroll
        for (int off=8; off>=1; off>>=1) vsum += __shfl_xor_sync(0xffffffffu, vsum, off);
        float rstd = rsqrtf(vsum*(1.0f/DIM) + 1e-5f);
        #pragma unroll
        for (int j=0;j<4;j++){
            float4 g  = *(const float4*)(gamma + 4*tx + 64*j);
            float4 bt = *(const float4*)(beta  + 4*tx + 64*j);
            float4 h  = acc[i][j]; float4 y;
            y.x=(h.x-mu)*rstd*g.x+bt.x; y.x=(y.x>=0.f)?y.x:0.01f*y.x;
            y.y=(h.y-mu)*rstd*g.y+bt.y; y.y=(y.y>=0.f)?y.y:0.01f*y.y;
            y.z=(h.z-mu)*rstd*g.z+bt.z; y.z=(y.z>=0.f)?y.z:0.01f*y.z;
            y.w=(h.w-mu)*rstd*g.w+bt.w; y.w=(y.w>=0.f)?y.w:0.01f*y.w;
            *(float4*)(out + (size_t)(r0+4*ty+i)*DIM + 4*tx + 64*j) = y;
        }
    }
}

// ---------------- entry ----------------
extern "C" void kernel_launch(void* const* d_in, const int* in_sizes, int n_in,
                              void* d_out, int out_size){
    const float* x     = (const float*)d_in[0];
    const float* Wq    = (const float*)d_in[1];
    const float* bq    = (const float*)d_in[2];
    const float* Wk    = (const float*)d_in[3];
    const float* bk    = (const float*)d_in[4];
    const float* Wv    = (const float*)d_in[5];
    const float* bv    = (const float*)d_in[6];
    const float* bo    = (const float*)d_in[8];
    const float* gamma = (const float*)d_in[9];
    const float* beta  = (const float*)d_in[10];
    float* out = (float*)d_out;

    cudaFuncSetAttribute(attn_wmma_kernel, cudaFuncAttributeMaxDynamicSharedMemorySize, SMEM_ATTN);

    transpose_w_kernel<<<4, 256>>>((const float*)d_in[1], (const float*)d_in[3],
                                   (const float*)d_in[5], (const float*)d_in[7]);
    qkv_kernel<<<dim3(ROWS/64, 3), 256>>>(x, bq, bk, bv);
    attn_wmma_kernel<<<dim3(SEQ/64, BATCH), 256, SMEM_ATTN>>>();
    proj_ln_kernel<<<ROWS/64, 256>>>(bo, gamma, beta, out);
    (void)Wq; (void)Wk; (void)Wv;
}

// round 11
// speedup vs baseline: 1.9004x; 1.1147x over previous
#include <cuda_runtime.h>
#include <cuda_bf16.h>
#include <mma.h>
#include <math.h>
#include <stdint.h>
using namespace nvcuda;

#define BATCH 8
#define SEQ   2048
#define DIM   256
#define ROWS  (BATCH*SEQ)
#define LOG2E 1.4426950408889634f

__device__ __align__(16) float g_WT[4*DIM*DIM];
__device__ __align__(16) float g_loc[ROWS*DIM];
__device__ __align__(16) __nv_bfloat16 g_WTh[4*DIM*DIM], g_WTl[4*DIM*DIM];
__device__ __align__(16) __nv_bfloat16 g_Xh[ROWS*DIM], g_Xl[ROWS*DIM];
__device__ __align__(16) __nv_bfloat16 g_Qh[ROWS*DIM], g_Ql[ROWS*DIM];
__device__ __align__(16) __nv_bfloat16 g_Kh[ROWS*DIM], g_Kl[ROWS*DIM];
__device__ __align__(16) __nv_bfloat16 g_Vh[ROWS*DIM], g_Vl[ROWS*DIM];

__device__ __forceinline__ float fexp2(float x){ float y; asm("ex2.approx.ftz.f32 %0, %1;" : "=f"(y) : "f"(x)); return y; }
#define FMA4(o,a,b) do{ (o).x=fmaf((a),(b).x,(o).x); (o).y=fmaf((a),(b).y,(o).y); \
                        (o).z=fmaf((a),(b).z,(o).z); (o).w=fmaf((a),(b).w,(o).w);}while(0)

__device__ __forceinline__ uint32_t packbf(__nv_bfloat16 a, __nv_bfloat16 b){
    return (uint32_t)__bfloat16_as_ushort(a) | ((uint32_t)__bfloat16_as_ushort(b)<<16);
}
__device__ __forceinline__ void split4(float4 v, uint2& h, uint2& l){
    __nv_bfloat16 hx=__float2bfloat16(v.x), hy=__float2bfloat16(v.y), hz=__float2bfloat16(v.z), hw=__float2bfloat16(v.w);
    h.x = packbf(hx,hy); h.y = packbf(hz,hw);
    l.x = packbf(__float2bfloat16(v.x-__bfloat162float(hx)), __float2bfloat16(v.y-__bfloat162float(hy)));
    l.y = packbf(__float2bfloat16(v.z-__bfloat162float(hz)), __float2bfloat16(v.w-__bfloat162float(hw)));
}
__device__ __forceinline__ void cp16(void* s, const void* g){
    uint32_t a = (uint32_t)__cvta_generic_to_shared(s);
    asm volatile("cp.async.cg.shared.global [%0], [%1], 16;" :: "r"(a), "l"(g) : "memory");
}
#define CP_COMMIT() asm volatile("cp.async.commit_group;" ::: "memory")
#define CP_WAIT1()  asm volatile("cp.async.wait_group 1;" ::: "memory")
#define CP_WAIT0()  asm volatile("cp.async.wait_group 0;" ::: "memory")

// ---------------- weight transpose + hi/lo split ----------------
__global__ void transpose_w_kernel(const float* __restrict__ Wq, const float* __restrict__ Wk,
                                   const float* __restrict__ Wv, const float* __restrict__ Wo){
    int m = blockIdx.x;
    const float* W = (m==0)?Wq:((m==1)?Wk:((m==2)?Wv:Wo));
    float* WT = g_WT + (size_t)m*DIM*DIM;
    __nv_bfloat16* WTh = g_WTh + (size_t)m*DIM*DIM;
    __nv_bfloat16* WTl = g_WTl + (size_t)m*DIM*DIM;
    for (int idx = threadIdx.x; idx < DIM*DIM; idx += blockDim.x){
        float w = W[(idx&255)*DIM + (idx>>8)];
        WT[idx] = w;
        __nv_bfloat16 h = __float2bfloat16(w);
        WTh[idx] = h;
        WTl[idx] = __float2bfloat16(w - __bfloat162float(h));
    }
}
// ---------------- x hi/lo split ----------------
__global__ void split_x_kernel(const float* __restrict__ x){
    int idx = blockIdx.x*blockDim.x + threadIdx.x;     // one float4 each
    float4 v = *(const float4*)(x + (size_t)idx*4);
    uint2 h,l; split4(v,h,l);
    *(uint2*)(g_Xh + (size_t)idx*4) = h;
    *(uint2*)(g_Xl + (size_t)idx*4) = l;
}

// ---------------- QKV projections: bf16-split WMMA ----------------
#define XS 72
#define WS 264
#define QK_XH 0
#define QK_XL 9216
#define QK_W  18432
#define QK_WL (QK_W + 33792)
#define SMEM_QKV (QK_W + 67584)     // 86016

__global__ void __launch_bounds__(256,1) qkv_wmma_kernel(
        const float* __restrict__ bq, const float* __restrict__ bk, const float* __restrict__ bv){
    extern __shared__ char smch[];
    __nv_bfloat16* Xh = (__nv_bfloat16*)(smch+QK_XH);
    __nv_bfloat16* Xl = (__nv_bfloat16*)(smch+QK_XL);
    __nv_bfloat16* Wh = (__nv_bfloat16*)(smch+QK_W);
    __nv_bfloat16* Wl = (__nv_bfloat16*)(smch+QK_WL);
    float* Of = (float*)(smch+QK_W);
    int tid = threadIdx.x, wid = tid>>5;
    int m = blockIdx.y, r0 = blockIdx.x*64;
    int mw = wid&3, np = wid>>2;
    const __nv_bfloat16* WTh = g_WTh + (size_t)m*DIM*DIM;
    const __nv_bfloat16* WTl = g_WTl + (size_t)m*DIM*DIM;

    wmma::fragment<wmma::accumulator,16,16,16,float> acc[8];
    #pragma unroll
    for (int j=0;j<8;j++) wmma::fill_fragment(acc[j], 0.f);

    for (int ck = 0; ck < 4; ++ck){
        __syncthreads();
        #pragma unroll
        for (int it=0; it<2; ++it){
            int idx = tid + it*256;           // 0..511
            int r = idx>>3, c8 = idx&7;
            size_t gsrc = (size_t)(r0+r)*DIM + ck*64 + c8*8;
            *(uint4*)(Xh + r*XS + c8*8) = *(const uint4*)(g_Xh + gsrc);
            *(uint4*)(Xl + r*XS + c8*8) = *(const uint4*)(g_Xl + gsrc);
        }
        #pragma unroll
        for (int it=0; it<8; ++it){
            int idx = tid + it*256;           // 0..2047
            int dd = idx>>5, c8 = idx&31;
            size_t gsrc = (size_t)(ck*64+dd)*DIM + c8*8;
            *(uint4*)(Wh + dd*WS + c8*8) = *(const uint4*)(WTh + gsrc);
            *(uint4*)(Wl + dd*WS + c8*8) = *(const uint4*)(WTl + gsrc);
        }
        __syncthreads();
        #pragma unroll
        for (int k=0;k<4;++k){
            wmma::fragment<wmma::matrix_a,16,16,16,__nv_bfloat16,wmma::row_major> ah, al;
            wmma::load_matrix_sync(ah, Xh + mw*16*XS + k*16, XS);
            wmma::load_matrix_sync(al, Xl + mw*16*XS + k*16, XS);
            #pragma unroll
            for (int j=0;j<8;++j){
                int n0 = np*128 + j*16;
                wmma::fragment<wmma::matrix_b,16,16,16,__nv_bfloat16,wmma::row_major> bh, bl;
                wmma::load_matrix_sync(bh, Wh + k*16*WS + n0, WS);
                wmma::load_matrix_sync(bl, Wl + k*16*WS + n0, WS);
                wmma::mma_sync(acc[j], ah, bh, acc[j]);
                wmma::mma_sync(acc[j], al, bh, acc[j]);
                wmma::mma_sync(acc[j], ah, bl, acc[j]);
            }
        }
    }
    __syncthreads();
    #pragma unroll
    for (int j=0;j<8;++j)
        wmma::store_matrix_sync(Of + mw*16*WS + np*128 + j*16, acc[j], WS, wmma::mem_row_major);
    __syncthreads();

    const float* bias = (m==0)?bq:((m==1)?bk:bv);
    __nv_bfloat16* oh = (m==0)?g_Qh:((m==1)?g_Kh:g_Vh);
    __nv_bfloat16* ol = (m==0)?g_Ql:((m==1)?g_Kl:g_Vl);
    int row = tid>>2, part = tid&3;
    #pragma unroll
    for (int c4=0;c4<16;++c4){
        float4 v = *(const float4*)(Of + row*WS + part*64 + c4*4);
        float4 bb = *(const float4*)(bias + part*64 + c4*4);
        v.x+=bb.x; v.y+=bb.y; v.z+=bb.z; v.w+=bb.w;
        uint2 h,l; split4(v,h,l);
        size_t off = (size_t)(r0+row)*DIM + part*64 + c4*4;
        *(uint2*)(oh+off) = h; *(uint2*)(ol+off) = l;
    }
}

// ---------------- WMMA bf16-split flash attention, cp.async pipelined ----------------
#define QS 264
#define PS 72
#define A_QH 0
#define A_QL 33792
#define A_K  67584        // Kh | Kl  (O f32 overlays at end)
#define A_V  135168       // Vh | Vl
#define A_SS 202752       // f32 S 18432 ; Ph overlays at +0 (9216), Pl at +9216
#define A_LS 221184
#define SMEM_ATTN 221440

__device__ __forceinline__ void stage64(__nv_bfloat16* s, const __nv_bfloat16* g, int tid){
    #pragma unroll
    for (int it=0; it<8; ++it){
        int idx = tid + it*256;
        int r = idx>>5, c8 = idx&31;
        *(uint4*)(s + r*QS + c8*8) = *(const uint4*)(g + (size_t)r*DIM + c8*8);
    }
}
__device__ __forceinline__ void stage64_async(__nv_bfloat16* s, const __nv_bfloat16* g, int tid){
    #pragma unroll
    for (int it=0; it<8; ++it){
        int idx = tid + it*256;
        int r = idx>>5, c8 = idx&31;
        cp16(s + r*QS + c8*8, g + (size_t)r*DIM + c8*8);
    }
}

__global__ void __launch_bounds__(256,1) attn_wmma_kernel(){
    extern __shared__ char smch[];
    __nv_bfloat16* Qh = (__nv_bfloat16*)(smch+A_QH);
    __nv_bfloat16* Ql = (__nv_bfloat16*)(smch+A_QL);
    __nv_bfloat16* Kh = (__nv_bfloat16*)(smch+A_K);
    __nv_bfloat16* Kl = Kh + 64*QS;
    __nv_bfloat16* Vh = (__nv_bfloat16*)(smch+A_V);
    __nv_bfloat16* Vl = Vh + 64*QS;
    float* Of = (float*)(smch+A_K);
    float* Ss = (float*)(smch+A_SS);
    __nv_bfloat16* Ph = (__nv_bfloat16*)(smch+A_SS);
    __nv_bfloat16* Pl = (__nv_bfloat16*)(smch+A_SS+9216);
    float* lsum = (float*)(smch+A_LS);

    int tid = threadIdx.x, wid = tid>>5;
    int b = blockIdx.y, q0 = blockIdx.x*64;
    int mw = wid&3, np = wid>>2;
    int row = tid>>2, part = tid&3;
    size_t bb = (size_t)b*SEQ*DIM;

    // prologue: async K0, then Q (regular), lsum
    stage64_async(Kh, g_Kh + bb, tid);
    stage64_async(Kl, g_Kl + bb, tid);
    CP_COMMIT();
    stage64(Qh, g_Qh + bb + (size_t)q0*DIM, tid);
    stage64(Ql, g_Ql + bb + (size_t)q0*DIM, tid);
    if (tid < 64) lsum[tid] = 0.f;

    wmma::fragment<wmma::accumulator,16,16,16,float> o[8];
    #pragma unroll
    for (int j=0;j<8;j++) wmma::fill_fragment(o[j], 0.f);

    for (int kt = 0; kt < SEQ/64; ++kt){
        size_t kb = bb + (size_t)kt*64*DIM;
        // prefetch V(kt)
        stage64_async(Vh, g_Vh + kb, tid);
        stage64_async(Vl, g_Vl + kb, tid);
        CP_COMMIT();
        CP_WAIT1();                 // K(kt) arrived (V may be in flight)
        __syncthreads();

        // ---- S = (Qh+Ql)(Kh+Kl)^T, 3 terms ----
        wmma::fragment<wmma::accumulator,16,16,16,float> c[2];
        wmma::fill_fragment(c[0], 0.f);
        wmma::fill_fragment(c[1], 0.f);
        #pragma unroll
        for (int k=0;k<16;++k){
            wmma::fragment<wmma::matrix_a,16,16,16,__nv_bfloat16,wmma::row_major> ah, al;
            wmma::load_matrix_sync(ah, Qh + mw*16*QS + k*16, QS);
            wmma::load_matrix_sync(al, Ql + mw*16*QS + k*16, QS);
            #pragma unroll
            for (int j=0;j<2;++j){
                int n0 = (np*2+j)*16;
                wmma::fragment<wmma::matrix_b,16,16,16,__nv_bfloat16,wmma::col_major> bh, bl;
                wmma::load_matrix_sync(bh, Kh + n0*QS + k*16, QS);
                wmma::load_matrix_sync(bl, Kl + n0*QS + k*16, QS);
                wmma::mma_sync(c[j], ah, bh, c[j]);
                wmma::mma_sync(c[j], al, bh, c[j]);
                wmma::mma_sync(c[j], ah, bl, c[j]);
            }
        }
        #pragma unroll
        for (int j=0;j<2;++j)
            wmma::store_matrix_sync(Ss + mw*16*PS + (np*2+j)*16, c[j], PS, wmma::mem_row_major);
        __syncthreads();

        // prefetch K(kt+1) — K buffer free now
        if (kt < SEQ/64-1){
            size_t kbn = kb + (size_t)64*DIM;
            stage64_async(Kh, g_Kh + kbn, tid);
            stage64_async(Kl, g_Kl + kbn, tid);
            CP_COMMIT();
        }

        // ---- softmax: read S to regs, then overlay P on the S buffer ----
        float sv[16];
        #pragma unroll
        for (int c2=0;c2<16;++c2) sv[c2] = Ss[row*PS + part*16 + c2];
        __syncthreads();
        {
            float psum = 0.f;
            __nv_bfloat16* phr = Ph + row*PS + part*16;
            __nv_bfloat16* plr = Pl + row*PS + part*16;
            #pragma unroll
            for (int c2=0;c2<16;++c2){
                float p = fexp2(sv[c2]*LOG2E);
                psum += p;
                __nv_bfloat16 h = __float2bfloat16(p);
                phr[c2] = h;
                plr[c2] = __float2bfloat16(p - __bfloat162float(h));
            }
            psum += __shfl_xor_sync(0xffffffffu, psum, 1);
            psum += __shfl_xor_sync(0xffffffffu, psum, 2);
            if (part == 0) lsum[row] += psum;
        }
        __syncthreads();

        if (kt < SEQ/64-1) { CP_WAIT1(); } else { CP_WAIT0(); }   // V(kt) arrived
        __syncthreads();

        // ---- O += (Ph+Pl)(Vh+Vl), 3 terms, register accumulation ----
        #pragma unroll
        for (int k=0;k<4;++k){
            wmma::fragment<wmma::matrix_a,16,16,16,__nv_bfloat16,wmma::row_major> ah, al;
            wmma::load_matrix_sync(ah, Ph + mw*16*PS + k*16, PS);
            wmma::load_matrix_sync(al, Pl + mw*16*PS + k*16, PS);
            #pragma unroll
            for (int j=0;j<8;++j){
                int n0 = (np*8+j)*16;
                wmma::fragment<wmma::matrix_b,16,16,16,__nv_bfloat16,wmma::row_major> bh, bl;
                wmma::load_matrix_sync(bh, Vh + k*16*QS + n0, QS);
                wmma::load_matrix_sync(bl, Vl + k*16*QS + n0, QS);
                wmma::mma_sync(o[j], ah, bh, o[j]);
                wmma::mma_sync(o[j], al, bh, o[j]);
                wmma::mma_sync(o[j], ah, bl, o[j]);
            }
        }
        __syncthreads();    // PV reads done before next V prefetch overwrites
    }

    #pragma unroll
    for (int j=0;j<8;++j)
        wmma::store_matrix_sync(Of + mw*16*QS + (np*8+j)*16, o[j], QS, wmma::mem_row_major);
    __syncthreads();
    {
        float inv = 1.0f / lsum[row];
        const float* orow = Of + row*QS + part*64;
        float* gout = g_loc + (size_t)(b*SEQ+q0+row)*DIM + part*64;
        #pragma unroll
        for (int c4=0;c4<16;++c4){
            float4 v = *(const float4*)(orow + c4*4);
            v.x*=inv; v.y*=inv; v.z*=inv; v.w*=inv;
            *(float4*)(gout + c4*4) = v;
        }
    }
}

// ---------------- fp32 64x256 GEMM mainloop (proj) ----------------
__device__ __forceinline__ void gemm64x256(const float* __restrict__ A, int r0, const float* __restrict__ WT,
                                           float* Xs, float* WsT, int tx, int ty, int tid, float4 acc[4][4]){
    for (int dc = 0; dc < 8; ++dc){
        #pragma unroll
        for (int it = 0; it < 2; ++it){
            int idx = tid + it*256; int r = idx>>3, d4 = idx&7;
            float4 v = *(const float4*)(A + (size_t)(r0+r)*DIM + dc*32 + d4*4);
            float* p = &Xs[r*33 + d4*4]; p[0]=v.x; p[1]=v.y; p[2]=v.z; p[3]=v.w;
        }
        #pragma unroll
        for (int it = 0; it < 8; ++it){
            int idx = tid + it*256; int dd = idx>>6, c4 = idx&63;
            *(float4*)&WsT[dd*256 + c4*4] = *(const float4*)(WT + (size_t)(dc*32+dd)*DIM + c4*4);
        }
        __syncthreads();
        #pragma unroll 8
        for (int dd = 0; dd < 32; ++dd){
            float a[4];
            #pragma unroll
            for (int i = 0; i < 4; ++i) a[i] = Xs[(4*ty+i)*33 + dd];
            #pragma unroll
            for (int j = 0; j < 4; ++j){
                float4 b = *(float4*)&WsT[dd*256 + 4*tx + 64*j];
                #pragma unroll
                for (int i = 0; i < 4; ++i) FMA4(acc[i][j], a[i], b);
            }
        }
        __syncthreads();
    }
}

// ---------------- output projection + LayerNorm + LeakyReLU ----------------
__global__ __launch_bounds__(256) void proj_ln_kernel(const float* __restrict__ bo,
        const float* __restrict__ gamma, const float* __restrict__ beta, float* __restrict__ out){
    __shared__ float Xs[64*33];
    __shared__ float WsT[32*256];
    const float* WT = g_WT + (size_t)3*DIM*DIM;
    int r0 = blockIdx.x*64;
    int tid = threadIdx.x, tx = tid&15, ty = tid>>4;
    float4 acc[4][4];
    #pragma unroll
    for (int i=0;i<4;i++){ acc[i][0]=acc[i][1]=acc[i][2]=acc[i][3]=make_float4(0.f,0.f,0.f,0.f); }
    gemm64x256(g_loc, r0, WT, Xs, WsT, tx, ty, tid, acc);
    #pragma unroll
    for (int j=0;j<4;j++){
        float4 bbv = *(const float4*)(bo + 4*tx + 64*j);
        #pragma unroll
        for (int i=0;i<4;i++){ acc[i][j].x+=bbv.x; acc[i][j].y+=bbv.y; acc[i][j].z+=bbv.z; acc[i][j].w+=bbv.w; }
    }
    #pragma unroll
    for (int i=0;i<4;i++){
        float ssum = 0.f;
        #pragma unroll
        for (int j=0;j<4;j++) ssum += acc[i][j].x + acc[i][j].y + acc[i][j].z + acc[i][j].w;
        #pragma unroll
        for (int off=8; off>=1; off>>=1) ssum += __shfl_xor_sync(0xffffffffu, ssum, off);
        float mu = ssum * (1.0f/DIM);
        float vsum = 0.f;
        #pragma unroll
        for (int j=0;j<4;j++){
            float dx=acc[i][j].x-mu, dy=acc[i][j].y-mu, dz=acc[i][j].z-mu, dw=acc[i][j].w-mu;
            vsum += dx*dx + dy*dy + dz*dz + dw*dw;
        }
        #pragma unroll
        for (int off=8; off>=1; off>>=1) vsum += __shfl_xor_sync(0xffffffffu, vsum, off);
        float rstd = rsqrtf(vsum*(1.0f/DIM) + 1e-5f);
        #pragma unroll
        for (int j=0;j<4;j++){
            float4 g  = *(const float4*)(gamma + 4*tx + 64*j);
            float4 bt = *(const float4*)(beta  + 4*tx + 64*j);
            float4 h  = acc[i][j]; float4 y;
            y.x=(h.x-mu)*rstd*g.x+bt.x; y.x=(y.x>=0.f)?y.x:0.01f*y.x;
            y.y=(h.y-mu)*rstd*g.y+bt.y; y.y=(y.y>=0.f)?y.y:0.01f*y.y;
            y.z=(h.z-mu)*rstd*g.z+bt.z; y.z=(y.z>=0.f)?y.z:0.01f*y.z;
            y.w=(h.w-mu)*rstd*g.w+bt.w; y.w=(y.w>=0.f)?y.w:0.01f*y.w;
            *(float4*)(out + (size_t)(r0+4*ty+i)*DIM + 4*tx + 64*j) = y;
        }
    }
}

// ---------------- entry ----------------
extern "C" void kernel_launch(void* const* d_in, const int* in_sizes, int n_in,
                              void* d_out, int out_size){
    const float* x     = (const float*)d_in[0];
    const float* bq    = (const float*)d_in[2];
    const float* bk    = (const float*)d_in[4];
    const float* bv    = (const float*)d_in[6];
    const float* bo    = (const float*)d_in[8];
    const float* gamma = (const float*)d_in[9];
    const float* beta  = (const float*)d_in[10];
    float* out = (float*)d_out;

    cudaFuncSetAttribute(qkv_wmma_kernel, cudaFuncAttributeMaxDynamicSharedMemorySize, SMEM_QKV);
    cudaFuncSetAttribute(attn_wmma_kernel, cudaFuncAttributeMaxDynamicSharedMemorySize, SMEM_ATTN);

    transpose_w_kernel<<<4, 256>>>((const float*)d_in[1], (const float*)d_in[3],
                                   (const float*)d_in[5], (const float*)d_in[7]);
    split_x_kernel<<<ROWS*DIM/4/256, 256>>>(x);
    qkv_wmma_kernel<<<dim3(ROWS/64, 3), 256, SMEM_QKV>>>(bq, bk, bv);
    attn_wmma_kernel<<<dim3(SEQ/64, BATCH), 256, SMEM_ATTN>>>();
    proj_ln_kernel<<<ROWS/64, 256>>>(bo, gamma, beta, out);
}

// round 12
// speedup vs baseline: 1.9043x; 1.0020x over previous
#include <cuda_runtime.h>
#include <cuda_bf16.h>
#include <mma.h>
#include <math.h>
#include <stdint.h>
using namespace nvcuda;

#define BATCH 8
#define SEQ   2048
#define DIM   256
#define ROWS  (BATCH*SEQ)
#define LOG2E 1.4426950408889634f

__device__ __align__(16) float g_WT[4*DIM*DIM];
__device__ __align__(16) float g_loc[ROWS*DIM];
__device__ __align__(16) __nv_bfloat16 g_WTh[4*DIM*DIM], g_WTl[4*DIM*DIM];
__device__ __align__(16) __nv_bfloat16 g_Xh[ROWS*DIM], g_Xl[ROWS*DIM];
__device__ __align__(16) __nv_bfloat16 g_Qh[ROWS*DIM], g_Ql[ROWS*DIM];
__device__ __align__(16) __nv_bfloat16 g_Kh[ROWS*DIM], g_Kl[ROWS*DIM];
__device__ __align__(16) __nv_bfloat16 g_Vh[ROWS*DIM], g_Vl[ROWS*DIM];

__device__ __forceinline__ float fexp2(float x){ float y; asm("ex2.approx.ftz.f32 %0, %1;" : "=f"(y) : "f"(x)); return y; }
#define FMA4(o,a,b) do{ (o).x=fmaf((a),(b).x,(o).x); (o).y=fmaf((a),(b).y,(o).y); \
                        (o).z=fmaf((a),(b).z,(o).z); (o).w=fmaf((a),(b).w,(o).w);}while(0)

__device__ __forceinline__ uint32_t packbf(__nv_bfloat16 a, __nv_bfloat16 b){
    return (uint32_t)__bfloat16_as_ushort(a) | ((uint32_t)__bfloat16_as_ushort(b)<<16);
}
__device__ __forceinline__ void split4(float4 v, uint2& h, uint2& l){
    __nv_bfloat16 hx=__float2bfloat16(v.x), hy=__float2bfloat16(v.y), hz=__float2bfloat16(v.z), hw=__float2bfloat16(v.w);
    h.x = packbf(hx,hy); h.y = packbf(hz,hw);
    l.x = packbf(__float2bfloat16(v.x-__bfloat162float(hx)), __float2bfloat16(v.y-__bfloat162float(hy)));
    l.y = packbf(__float2bfloat16(v.z-__bfloat162float(hz)), __float2bfloat16(v.w-__bfloat162float(hw)));
}
__device__ __forceinline__ void cp16(void* s, const void* g){
    uint32_t a = (uint32_t)__cvta_generic_to_shared(s);
    asm volatile("cp.async.cg.shared.global [%0], [%1], 16;" :: "r"(a), "l"(g) : "memory");
}
#define CP_COMMIT() asm volatile("cp.async.commit_group;" ::: "memory")
#define CP_WAIT1()  asm volatile("cp.async.wait_group 1;" ::: "memory")
#define CP_WAIT0()  asm volatile("cp.async.wait_group 0;" ::: "memory")

// ---------------- weight transpose + hi/lo split ----------------
__global__ void transpose_w_kernel(const float* __restrict__ Wq, const float* __restrict__ Wk,
                                   const float* __restrict__ Wv, const float* __restrict__ Wo){
    int m = blockIdx.x;
    const float* W = (m==0)?Wq:((m==1)?Wk:((m==2)?Wv:Wo));
    float* WT = g_WT + (size_t)m*DIM*DIM;
    __nv_bfloat16* WTh = g_WTh + (size_t)m*DIM*DIM;
    __nv_bfloat16* WTl = g_WTl + (size_t)m*DIM*DIM;
    for (int idx = threadIdx.x; idx < DIM*DIM; idx += blockDim.x){
        float w = W[(idx&255)*DIM + (idx>>8)];
        WT[idx] = w;
        __nv_bfloat16 h = __float2bfloat16(w);
        WTh[idx] = h;
        WTl[idx] = __float2bfloat16(w - __bfloat162float(h));
    }
}
// ---------------- x hi/lo split ----------------
__global__ void split_x_kernel(const float* __restrict__ x){
    int idx = blockIdx.x*blockDim.x + threadIdx.x;
    float4 v = *(const float4*)(x + (size_t)idx*4);
    uint2 h,l; split4(v,h,l);
    *(uint2*)(g_Xh + (size_t)idx*4) = h;
    *(uint2*)(g_Xl + (size_t)idx*4) = l;
}

// ---------------- QKV projections: bf16-split WMMA ----------------
#define XS 72
#define WS 264
#define QK_XH 0
#define QK_XL 9216
#define QK_W  18432
#define QK_WL (QK_W + 33792)
#define SMEM_QKV (QK_W + 67584)

__global__ void __launch_bounds__(256,1) qkv_wmma_kernel(
        const float* __restrict__ bq, const float* __restrict__ bk, const float* __restrict__ bv){
    extern __shared__ char smch[];
    __nv_bfloat16* Xh = (__nv_bfloat16*)(smch+QK_XH);
    __nv_bfloat16* Xl = (__nv_bfloat16*)(smch+QK_XL);
    __nv_bfloat16* Wh = (__nv_bfloat16*)(smch+QK_W);
    __nv_bfloat16* Wl = (__nv_bfloat16*)(smch+QK_WL);
    float* Of = (float*)(smch+QK_W);
    int tid = threadIdx.x, wid = tid>>5;
    int m = blockIdx.y, r0 = blockIdx.x*64;
    int mw = wid&3, np = wid>>2;
    const __nv_bfloat16* WTh = g_WTh + (size_t)m*DIM*DIM;
    const __nv_bfloat16* WTl = g_WTl + (size_t)m*DIM*DIM;

    wmma::fragment<wmma::accumulator,16,16,16,float> acc[8];
    #pragma unroll
    for (int j=0;j<8;j++) wmma::fill_fragment(acc[j], 0.f);

    for (int ck = 0; ck < 4; ++ck){
        __syncthreads();
        #pragma unroll
        for (int it=0; it<2; ++it){
            int idx = tid + it*256;
            int r = idx>>3, c8 = idx&7;
            size_t gsrc = (size_t)(r0+r)*DIM + ck*64 + c8*8;
            *(uint4*)(Xh + r*XS + c8*8) = *(const uint4*)(g_Xh + gsrc);
            *(uint4*)(Xl + r*XS + c8*8) = *(const uint4*)(g_Xl + gsrc);
        }
        #pragma unroll
        for (int it=0; it<8; ++it){
            int idx = tid + it*256;
            int dd = idx>>5, c8 = idx&31;
            size_t gsrc = (size_t)(ck*64+dd)*DIM + c8*8;
            *(uint4*)(Wh + dd*WS + c8*8) = *(const uint4*)(WTh + gsrc);
            *(uint4*)(Wl + dd*WS + c8*8) = *(const uint4*)(WTl + gsrc);
        }
        __syncthreads();
        #pragma unroll
        for (int k=0;k<4;++k){
            wmma::fragment<wmma::matrix_a,16,16,16,__nv_bfloat16,wmma::row_major> ah, al;
            wmma::load_matrix_sync(ah, Xh + mw*16*XS + k*16, XS);
            wmma::load_matrix_sync(al, Xl + mw*16*XS + k*16, XS);
            #pragma unroll
            for (int j=0;j<8;++j){
                int n0 = np*128 + j*16;
                wmma::fragment<wmma::matrix_b,16,16,16,__nv_bfloat16,wmma::row_major> bh, bl;
                wmma::load_matrix_sync(bh, Wh + k*16*WS + n0, WS);
                wmma::load_matrix_sync(bl, Wl + k*16*WS + n0, WS);
                wmma::mma_sync(acc[j], ah, bh, acc[j]);
                wmma::mma_sync(acc[j], al, bh, acc[j]);
                wmma::mma_sync(acc[j], ah, bl, acc[j]);
            }
        }
    }
    __syncthreads();
    #pragma unroll
    for (int j=0;j<8;++j)
        wmma::store_matrix_sync(Of + mw*16*WS + np*128 + j*16, acc[j], WS, wmma::mem_row_major);
    __syncthreads();

    const float* bias = (m==0)?bq:((m==1)?bk:bv);
    __nv_bfloat16* oh = (m==0)?g_Qh:((m==1)?g_Kh:g_Vh);
    __nv_bfloat16* ol = (m==0)?g_Ql:((m==1)?g_Kl:g_Vl);
    int row = tid>>2, part = tid&3;
    #pragma unroll
    for (int c4=0;c4<16;++c4){
        float4 v = *(const float4*)(Of + row*WS + part*64 + c4*4);
        float4 bb = *(const float4*)(bias + part*64 + c4*4);
        v.x+=bb.x; v.y+=bb.y; v.z+=bb.z; v.w+=bb.w;
        uint2 h,l; split4(v,h,l);
        size_t off = (size_t)(r0+row)*DIM + part*64 + c4*4;
        *(uint2*)(oh+off) = h; *(uint2*)(ol+off) = l;
    }
}

// ---------------- WMMA bf16-split flash attention, cp.async pipelined ----------------
#define QS 264
#define PS 72
#define A_QH 0
#define A_QL 33792
#define A_K  67584
#define A_V  135168
#define A_SS 202752
#define A_LS 221184
#define SMEM_ATTN 221440

__device__ __forceinline__ void stage64(__nv_bfloat16* s, const __nv_bfloat16* g, int tid){
    #pragma unroll
    for (int it=0; it<8; ++it){
        int idx = tid + it*256;
        int r = idx>>5, c8 = idx&31;
        *(uint4*)(s + r*QS + c8*8) = *(const uint4*)(g + (size_t)r*DIM + c8*8);
    }
}
__device__ __forceinline__ void stage64_async(__nv_bfloat16* s, const __nv_bfloat16* g, int tid){
    #pragma unroll
    for (int it=0; it<8; ++it){
        int idx = tid + it*256;
        int r = idx>>5, c8 = idx&31;
        cp16(s + r*QS + c8*8, g + (size_t)r*DIM + c8*8);
    }
}

__global__ void __launch_bounds__(256,1) attn_wmma_kernel(){
    extern __shared__ char smch[];
    __nv_bfloat16* Qh = (__nv_bfloat16*)(smch+A_QH);
    __nv_bfloat16* Ql = (__nv_bfloat16*)(smch+A_QL);
    __nv_bfloat16* Kh = (__nv_bfloat16*)(smch+A_K);
    __nv_bfloat16* Kl = Kh + 64*QS;
    __nv_bfloat16* Vh = (__nv_bfloat16*)(smch+A_V);
    __nv_bfloat16* Vl = Vh + 64*QS;
    float* Of = (float*)(smch+A_K);
    float* Ss = (float*)(smch+A_SS);
    __nv_bfloat16* Ph = (__nv_bfloat16*)(smch+A_SS);
    __nv_bfloat16* Pl = (__nv_bfloat16*)(smch+A_SS+9216);
    float* lsum = (float*)(smch+A_LS);

    int tid = threadIdx.x, wid = tid>>5;
    int b = blockIdx.y, q0 = blockIdx.x*64;
    int mw = wid&3, np = wid>>2;
    int row = tid>>2, part = tid&3;
    size_t bb = (size_t)b*SEQ*DIM;

    stage64_async(Kh, g_Kh + bb, tid);
    stage64_async(Kl, g_Kl + bb, tid);
    CP_COMMIT();
    stage64(Qh, g_Qh + bb + (size_t)q0*DIM, tid);
    stage64(Ql, g_Ql + bb + (size_t)q0*DIM, tid);
    if (tid < 64) lsum[tid] = 0.f;

    wmma::fragment<wmma::accumulator,16,16,16,float> o[8];
    #pragma unroll
    for (int j=0;j<8;j++) wmma::fill_fragment(o[j], 0.f);

    for (int kt = 0; kt < SEQ/64; ++kt){
        size_t kb = bb + (size_t)kt*64*DIM;
        stage64_async(Vh, g_Vh + kb, tid);
        stage64_async(Vl, g_Vl + kb, tid);
        CP_COMMIT();
        CP_WAIT1();
        __syncthreads();

        // ---- S = (Qh+Ql)(Kh+Kl)^T : 3 terms in SEPARATE accumulators (6 chains/warp) ----
        wmma::fragment<wmma::accumulator,16,16,16,float> chh[2], clh[2], chl[2];
        #pragma unroll
        for (int j=0;j<2;++j){
            wmma::fill_fragment(chh[j], 0.f);
            wmma::fill_fragment(clh[j], 0.f);
            wmma::fill_fragment(chl[j], 0.f);
        }
        #pragma unroll
        for (int k=0;k<16;++k){
            wmma::fragment<wmma::matrix_a,16,16,16,__nv_bfloat16,wmma::row_major> ah, al;
            wmma::load_matrix_sync(ah, Qh + mw*16*QS + k*16, QS);
            wmma::load_matrix_sync(al, Ql + mw*16*QS + k*16, QS);
            #pragma unroll
            for (int j=0;j<2;++j){
                int n0 = (np*2+j)*16;
                wmma::fragment<wmma::matrix_b,16,16,16,__nv_bfloat16,wmma::col_major> bh, bl;
                wmma::load_matrix_sync(bh, Kh + n0*QS + k*16, QS);
                wmma::load_matrix_sync(bl, Kl + n0*QS + k*16, QS);
                wmma::mma_sync(chh[j], ah, bh, chh[j]);
                wmma::mma_sync(clh[j], al, bh, clh[j]);
                wmma::mma_sync(chl[j], ah, bl, chl[j]);
            }
        }
        #pragma unroll
        for (int j=0;j<2;++j){
            #pragma unroll
            for (int t=0; t<chh[j].num_elements; ++t)
                chh[j].x[t] += clh[j].x[t] + chl[j].x[t];
            wmma::store_matrix_sync(Ss + mw*16*PS + (np*2+j)*16, chh[j], PS, wmma::mem_row_major);
        }
        __syncthreads();

        if (kt < SEQ/64-1){
            size_t kbn = kb + (size_t)64*DIM;
            stage64_async(Kh, g_Kh + kbn, tid);
            stage64_async(Kl, g_Kl + kbn, tid);
            CP_COMMIT();
        }

        // ---- softmax: read S to regs, overlay P on the S buffer ----
        float sv[16];
        #pragma unroll
        for (int c2=0;c2<16;++c2) sv[c2] = Ss[row*PS + part*16 + c2];
        __syncthreads();
        {
            float psum = 0.f;
            __nv_bfloat16* phr = Ph + row*PS + part*16;
            __nv_bfloat16* plr = Pl + row*PS + part*16;
            #pragma unroll
            for (int c2=0;c2<16;++c2){
                float p = fexp2(sv[c2]*LOG2E);
                psum += p;
                __nv_bfloat16 h = __float2bfloat16(p);
                phr[c2] = h;
                plr[c2] = __float2bfloat16(p - __bfloat162float(h));
            }
            psum += __shfl_xor_sync(0xffffffffu, psum, 1);
            psum += __shfl_xor_sync(0xffffffffu, psum, 2);
            if (part == 0) lsum[row] += psum;
        }
        __syncthreads();

        if (kt < SEQ/64-1) { CP_WAIT1(); } else { CP_WAIT0(); }
        __syncthreads();

        // ---- O += (Ph+Pl)(Vh+Vl) : 8 independent chains ----
        #pragma unroll
        for (int k=0;k<4;++k){
            wmma::fragment<wmma::matrix_a,16,16,16,__nv_bfloat16,wmma::row_major> ah, al;
            wmma::load_matrix_sync(ah, Ph + mw*16*PS + k*16, PS);
            wmma::load_matrix_sync(al, Pl + mw*16*PS + k*16, PS);
            #pragma unroll
            for (int j=0;j<8;++j){
                int n0 = (np*8+j)*16;
                wmma::fragment<wmma::matrix_b,16,16,16,__nv_bfloat16,wmma::row_major> bh, bl;
                wmma::load_matrix_sync(bh, Vh + k*16*QS + n0, QS);
                wmma::load_matrix_sync(bl, Vl + k*16*QS + n0, QS);
                wmma::mma_sync(o[j], ah, bh, o[j]);
                wmma::mma_sync(o[j], al, bh, o[j]);
                wmma::mma_sync(o[j], ah, bl, o[j]);
            }
        }
        __syncthreads();
    }

    #pragma unroll
    for (int j=0;j<8;++j)
        wmma::store_matrix_sync(Of + mw*16*QS + (np*8+j)*16, o[j], QS, wmma::mem_row_major);
    __syncthreads();
    {
        float inv = 1.0f / lsum[row];
        const float* orow = Of + row*QS + part*64;
        float* gout = g_loc + (size_t)(b*SEQ+q0+row)*DIM + part*64;
        #pragma unroll
        for (int c4=0;c4<16;++c4){
            float4 v = *(const float4*)(orow + c4*4);
            v.x*=inv; v.y*=inv; v.z*=inv; v.w*=inv;
            *(float4*)(gout + c4*4) = v;
        }
    }
}

// ---------------- fp32 64x256 GEMM mainloop (proj) ----------------
__device__ __forceinline__ void gemm64x256(const float* __restrict__ A, int r0, const float* __restrict__ WT,
                                           float* Xs, float* WsT, int tx, int ty, int tid, float4 acc[4][4]){
    for (int dc = 0; dc < 8; ++dc){
        #pragma unroll
        for (int it = 0; it < 2; ++it){
            int idx = tid + it*256; int r = idx>>3, d4 = idx&7;
            float4 v = *(const float4*)(A + (size_t)(r0+r)*DIM + dc*32 + d4*4);
            float* p = &Xs[r*33 + d4*4]; p[0]=v.x; p[1]=v.y; p[2]=v.z; p[3]=v.w;
        }
        #pragma unroll
        for (int it = 0; it < 8; ++it){
            int idx = tid + it*256; int dd = idx>>6, c4 = idx&63;
            *(float4*)&WsT[dd*256 + c4*4] = *(const float4*)(WT + (size_t)(dc*32+dd)*DIM + c4*4);
        }
        __syncthreads();
        #pragma unroll 8
        for (int dd = 0; dd < 32; ++dd){
            float a[4];
            #pragma unroll
            for (int i = 0; i < 4; ++i) a[i] = Xs[(4*ty+i)*33 + dd];
            #pragma unroll
            for (int j = 0; j < 4; ++j){
                float4 b = *(float4*)&WsT[dd*256 + 4*tx + 64*j];
                #pragma unroll
                for (int i = 0; i < 4; ++i) FMA4(acc[i][j], a[i], b);
            }
        }
        __syncthreads();
    }
}

// ---------------- output projection + LayerNorm + LeakyReLU ----------------
__global__ __launch_bounds__(256) void proj_ln_kernel(const float* __restrict__ bo,
        const float* __restrict__ gamma, const float* __restrict__ beta, float* __restrict__ out){
    __shared__ float Xs[64*33];
    __shared__ float WsT[32*256];
    const float* WT = g_WT + (size_t)3*DIM*DIM;
    int r0 = blockIdx.x*64;
    int tid = threadIdx.x, tx = tid&15, ty = tid>>4;
    float4 acc[4][4];
    #pragma unroll
    for (int i=0;i<4;i++){ acc[i][0]=acc[i][1]=acc[i][2]=acc[i][3]=make_float4(0.f,0.f,0.f,0.f); }
    gemm64x256(g_loc, r0, WT, Xs, WsT, tx, ty, tid, acc);
    #pragma unroll
    for (int j=0;j<4;j++){
        float4 bbv = *(const float4*)(bo + 4*tx + 64*j);
        #pragma unroll
        for (int i=0;i<4;i++){ acc[i][j].x+=bbv.x; acc[i][j].y+=bbv.y; acc[i][j].z+=bbv.z; acc[i][j].w+=bbv.w; }
    }
    #pragma unroll
    for (int i=0;i<4;i++){
        float ssum = 0.f;
        #pragma unroll
        for (int j=0;j<4;j++) ssum += acc[i][j].x + acc[i][j].y + acc[i][j].z + acc[i][j].w;
        #pragma unroll
        for (int off=8; off>=1; off>>=1) ssum += __shfl_xor_sync(0xffffffffu, ssum, off);
        float mu = ssum * (1.0f/DIM);
        float vsum = 0.f;
        #pragma unroll
        for (int j=0;j<4;j++){
            float dx=acc[i][j].x-mu, dy=acc[i][j].y-mu, dz=acc[i][j].z-mu, dw=acc[i][j].w-mu;
            vsum += dx*dx + dy*dy + dz*dz + dw*dw;
        }
        #pragma unroll
        for (int off=8; off>=1; off>>=1) vsum += __shfl_xor_sync(0xffffffffu, vsum, off);
        float rstd = rsqrtf(vsum*(1.0f/DIM) + 1e-5f);
        #pragma unroll
        for (int j=0;j<4;j++){
            float4 g  = *(const float4*)(gamma + 4*tx + 64*j);
            float4 bt = *(const float4*)(beta  + 4*tx + 64*j);
            float4 h  = acc[i][j]; float4 y;
            y.x=(h.x-mu)*rstd*g.x+bt.x; y.x=(y.x>=0.f)?y.x:0.01f*y.x;
            y.y=(h.y-mu)*rstd*g.y+bt.y; y.y=(y.y>=0.f)?y.y:0.01f*y.y;
            y.z=(h.z-mu)*rstd*g.z+bt.z; y.z=(y.z>=0.f)?y.z:0.01f*y.z;
            y.w=(h.w-mu)*rstd*g.w+bt.w; y.w=(y.w>=0.f)?y.w:0.01f*y.w;
            *(float4*)(out + (size_t)(r0+4*ty+i)*DIM + 4*tx + 64*j) = y;
        }
    }
}

// ---------------- entry ----------------
extern "C" void kernel_launch(void* const* d_in, const int* in_sizes, int n_in,
                              void* d_out, int out_size){
    const float* x     = (const float*)d_in[0];
    const float* bq    = (const float*)d_in[2];
    const float* bk    = (const float*)d_in[4];
    const float* bv    = (const float*)d_in[6];
    const float* bo    = (const float*)d_in[8];
    const float* gamma = (const float*)d_in[9];
    const float* beta  = (const float*)d_in[10];
    float* out = (float*)d_out;

    cudaFuncSetAttribute(qkv_wmma_kernel, cudaFuncAttributeMaxDynamicSharedMemorySize, SMEM_QKV);
    cudaFuncSetAttribute(attn_wmma_kernel, cudaFuncAttributeMaxDynamicSharedMemorySize, SMEM_ATTN);

    transpose_w_kernel<<<4, 256>>>((const float*)d_in[1], (const float*)d_in[3],
                                   (const float*)d_in[5], (const float*)d_in[7]);
    split_x_kernel<<<ROWS*DIM/4/256, 256>>>(x);
    qkv_wmma_kernel<<<dim3(ROWS/64, 3), 256, SMEM_QKV>>>(bq, bk, bv);
    attn_wmma_kernel<<<dim3(SEQ/64, BATCH), 256, SMEM_ATTN>>>();
    proj_ln_kernel<<<ROWS/64, 256>>>(bo, gamma, beta, out);
}